// round 6
// baseline (speedup 1.0000x reference)
#include <cuda_runtime.h>
#include <cuda_bf16.h>
#include <math.h>

#define B_ROWS 2048
#define C_COLS 32000
#define TPB 256
#define DEPTH 8
// 8000 float4 per row: 3 depth-8 batches (6144) + 7 strided (1792) + 64 tail
#define N4 (C_COLS / 4)

__device__ float g_row_loss[B_ROWS];
__device__ unsigned int g_done;        // zero-init at load; last CTA resets each run

// H(n): exact for small n, asymptotic otherwise (err < 1e-9, tolerance is 1e-3).
__device__ __forceinline__ float harmonic(int n) {
    if (n <= 0) return 0.0f;
    if (n < 32) {
        float h = 0.0f;
        #pragma unroll 1
        for (int i = 1; i <= n; ++i) h += 1.0f / (float)i;
        return h;
    }
    const float gamma = 0.57721566490153286f;
    float x = (float)n;
    float inv = 1.0f / x;
    float inv2 = inv * inv;
    return logf(x) + gamma + 0.5f * inv - (1.0f / 12.0f) * inv2
           + (1.0f / 120.0f) * inv2 * inv2;
}

__global__ void __launch_bounds__(TPB, 4) fused_kernel(const float* __restrict__ scores,
                                                       const int* __restrict__ targets,
                                                       float* __restrict__ out) {
    __shared__ float s_hs[TPB / 32];
    __shared__ int   s_cnt[TPB / 32];
    __shared__ bool  s_last;

    const int tid = threadIdx.x;
    const int b = blockIdx.x;
    const float* row = scores + (size_t)b * C_COLS;
    const int t = targets[b];
    const float gt = __ldg(row + t);              // same address -> broadcast
    const float c  = gt - 1.0f;                   // hinge: relu(v - c)

    const float4* row4 = reinterpret_cast<const float4*>(row);

    float hs0 = 0.0f, hs1 = 0.0f;
    int cnt = 0;

    // ---- main: 3 batches of DEPTH=8 front-loaded float4s (forces MLP_p1=8) ----
    #pragma unroll 1
    for (int bb = 0; bb < 3; ++bb) {
        const float4* p = row4 + bb * (DEPTH * TPB) + tid;
        float4 buf[DEPTH];
        #pragma unroll
        for (int k = 0; k < DEPTH; ++k) buf[k] = p[k * TPB];
        #pragma unroll
        for (int k = 0; k < DEPTH; ++k) {
            float4 v = buf[k];
            cnt += (v.x > gt) + (v.y > gt) + (v.z > gt) + (v.w > gt);
            hs0 += fmaxf(v.x - c, 0.0f);
            hs1 += fmaxf(v.y - c, 0.0f);
            hs0 += fmaxf(v.z - c, 0.0f);
            hs1 += fmaxf(v.w - c, 0.0f);
        }
    }

    // ---- 7 strided leftover iterations: indices 6144 .. 7935 ----
    {
        const float4* p = row4 + 3 * (DEPTH * TPB) + tid;   // 6144 + tid
        float4 buf[7];
        #pragma unroll
        for (int j = 0; j < 7; ++j) buf[j] = p[j * TPB];
        #pragma unroll
        for (int j = 0; j < 7; ++j) {
            float4 v = buf[j];
            cnt += (v.x > gt) + (v.y > gt) + (v.z > gt) + (v.w > gt);
            hs0 += fmaxf(v.x - c, 0.0f);
            hs1 += fmaxf(v.y - c, 0.0f);
            hs0 += fmaxf(v.z - c, 0.0f);
            hs1 += fmaxf(v.w - c, 0.0f);
        }
    }

    // ---- tail: 64 float4s at 7936..7999 ----
    if (tid < N4 - 7936) {
        float4 v = row4[7936 + tid];
        cnt += (v.x > gt) + (v.y > gt) + (v.z > gt) + (v.w > gt);
        hs0 += fmaxf(v.x - c, 0.0f);
        hs1 += fmaxf(v.y - c, 0.0f);
        hs0 += fmaxf(v.z - c, 0.0f);
        hs1 += fmaxf(v.w - c, 0.0f);
    }

    float hs = hs0 + hs1;
    #pragma unroll
    for (int off = 16; off > 0; off >>= 1) {
        hs  += __shfl_down_sync(0xFFFFFFFFu, hs,  off);
        cnt += __shfl_down_sync(0xFFFFFFFFu, cnt, off);
    }
    const int wid = tid >> 5;
    const int lid = tid & 31;
    if (lid == 0) { s_hs[wid] = hs; s_cnt[wid] = cnt; }
    __syncthreads();

    if (tid == 0) {
        float hsum = 0.0f;
        int   csum = 0;
        #pragma unroll
        for (int w = 0; w < TPB / 32; ++w) { hsum += s_hs[w]; csum += s_cnt[w]; }
        // target itself contributed relu(1) = 1 to hsum; remove it.
        float hinge = hsum - 1.0f;
        int rank = csum;                          // #(scores > gt)
        float weight = (rank == 0) ? 0.0f : harmonic(rank) / (float)rank;
        g_row_loss[b] = weight * hinge;
    }

    // ---- last-CTA deterministic final reduction ----
    if (tid == 0) {
        __threadfence();                          // publish g_row_loss
        unsigned int n = atomicAdd(&g_done, 1u);
        s_last = (n == B_ROWS - 1);
    }
    __syncthreads();

    if (s_last) {
        __shared__ float s_red[TPB];
        float acc = 0.0f;
        #pragma unroll
        for (int i = tid; i < B_ROWS; i += TPB) acc += g_row_loss[i];
        s_red[tid] = acc;
        __syncthreads();
        #pragma unroll
        for (int off = TPB / 2; off > 0; off >>= 1) {
            if (tid < off) s_red[tid] += s_red[tid + off];
            __syncthreads();
        }
        if (tid == 0) {
            out[0] = s_red[0] / (float)B_ROWS;
            g_done = 0;                           // reset for next graph replay
        }
    }
}

extern "C" void kernel_launch(void* const* d_in, const int* in_sizes, int n_in,
                              void* d_out, int out_size) {
    const float* scores  = (const float*)d_in[0];
    const int*   targets = (const int*)d_in[1];
    float* out = (float*)d_out;

    fused_kernel<<<B_ROWS, TPB>>>(scores, targets, out);
}